// round 12
// baseline (speedup 1.0000x reference)
#include <cuda_runtime.h>
#include <math.h>

// Problem constants
#define Bq 8
#define BH 4             // batch half
#define Pq 64
#define Vq 8
#define Lq 1024
#define Dq 256
#define NCHUNK 32
#define CLEN 32          // NCHUNK * CLEN == Lq
#define IY 4             // i-quarters per chunk block
#define SUB 8            // CLEN / IY
#define KSPLIT 8
#define KSEG 64          // 512 / KSPLIT
#define RG 4             // rows per projection block

// Scratch (static device globals; no allocation in kernel_launch)
__device__ float g_pr[Bq * NCHUNK * Dq];          // chunk partial sums (real)
__device__ float g_pi[Bq * NCHUNK * Dq];          // chunk partial sums (imag)
__device__ float g_ycat[Bq * Pq * 2 * Dq];        // [b, p, k] k<256: y_fwd, k>=256: y_bwd
__device__ float g_Wt[2 * Dq * Dq];               // W^T, [k][j]
__device__ float g_part[Bq * KSPLIT * Pq * Dq];   // split-k partials

// Host-side stream/events for graph fork-join (created at load time,
// before the harness takes its memory baseline; reused every call).
static cudaStream_t g_s1;
static cudaEvent_t g_evRoot, g_evC1, g_evF, g_evA;
namespace {
struct StreamInit {
    StreamInit() {
        cudaStreamCreateWithFlags(&g_s1, cudaStreamNonBlocking);
        cudaEventCreateWithFlags(&g_evRoot, cudaEventDisableTiming);
        cudaEventCreateWithFlags(&g_evC1, cudaEventDisableTiming);
        cudaEventCreateWithFlags(&g_evF, cudaEventDisableTiming);
        cudaEventCreateWithFlags(&g_evA, cudaEventDisableTiming);
    }
};
static StreamInit g_streamInit;
}

// ---------------------------------------------------------------------------
// Kernel 0: transpose proj_W [D, 2D] -> Wt [2D, D]
// ---------------------------------------------------------------------------
__global__ void k_transpose(const float* __restrict__ W) {
    int k = blockIdx.x;      // 0..511
    int j = threadIdx.x;     // 0..255
    g_Wt[k * Dq + j] = W[j * (2 * Dq) + k];
}

// ---------------------------------------------------------------------------
// Kernel 1: per-(b, chunk, d): Σ_{i<CLEN} λ_b^i * x̄[c*CLEN+i]
// 1024-thread block, 4 i-quarters combined via λ^8 Horner (R9-proven).
// b_off selects the batch half.
// ---------------------------------------------------------------------------
__global__ void __launch_bounds__(Dq * IY) k_chunks(
        const float* __restrict__ ts,
        const float* __restrict__ bnu,
        const float* __restrict__ btheta,
        const float* __restrict__ sig, int b_off) {
    __shared__ float s_r[IY - 1][Dq];
    __shared__ float s_i[IY - 1][Dq];
    const int d  = threadIdx.x;
    const int ty = threadIdx.y;        // i-quarter
    const int c  = blockIdx.x;         // chunk
    const int b  = blockIdx.y + b_off; // batch

    const float r  = expf(-expf(bnu[d]));
    float s_, c_;
    sincosf(btheta[d], &s_, &c_);
    const float lr = r * c_;
    const float li = r * s_;
    const float sg = sig[d];

    const float* base =
        ts + ((size_t)b * Lq + (size_t)c * CLEN + ty * SUB) * (Vq * Dq) + d;

    float wr = 1.f, wi = 0.f, ar = 0.f, ai = 0.f;
#pragma unroll
    for (int i = 0; i < SUB; i++) {
        const float* p = base + (size_t)i * (Vq * Dq);
        float xm = __ldg(p);
#pragma unroll
        for (int v = 1; v < Vq; v++) xm += __ldg(p + v * Dq);
        xm = fmaf(xm, 0.125f, sg);
        ar = fmaf(wr, xm, ar);
        ai = fmaf(wi, xm, ai);
        float t0 = wr * lr - wi * li;
        wi = fmaf(wr, li, wi * lr);
        wr = t0;
    }

    if (ty > 0) {
        s_r[ty - 1][d] = ar;
        s_i[ty - 1][d] = ai;
    }
    __syncthreads();

    if (ty == 0) {
        // q = lam^SUB via 3 squarings (SUB == 8)
        float qr = lr, qi = li;
#pragma unroll
        for (int s = 0; s < 3; s++) {
            float t0 = qr * qr - qi * qi;
            qi = 2.f * qr * qi;
            qr = t0;
        }
        // Horner: a = a0 + q*(a1 + q*(a2 + q*a3))
        float cr = s_r[2][d], ci = s_i[2][d];          // a3
        {
            float tr = s_r[1][d] + (qr * cr - qi * ci);
            float ti = s_i[1][d] + (qr * ci + qi * cr);
            cr = tr; ci = ti;
        }
        {
            float tr = s_r[0][d] + (qr * cr - qi * ci);
            float ti = s_i[0][d] + (qr * ci + qi * cr);
            cr = tr; ci = ti;
        }
        g_pr[(b * NCHUNK + c) * Dq + d] = ar + (qr * cr - qi * ci);
        g_pi[(b * NCHUNK + c) * Dq + d] = ai + (qr * ci + qi * cr);
    }
}

// ---------------------------------------------------------------------------
// Kernel 2a: forward scan, x batch-preloaded into registers (R11-proven).
// ---------------------------------------------------------------------------
__global__ void k_scan_fwd(const float* __restrict__ mem,
                           const float* __restrict__ fnu,
                           const float* __restrict__ ftheta,
                           const float* __restrict__ fgr,
                           const float* __restrict__ fgi,
                           const float* __restrict__ prefix) {
    const int d = threadIdx.x;
    const int b = blockIdx.x;
    const float pre = prefix[d];
    const float* xm = mem + (size_t)b * Pq * Dq + d;
    float* yc = g_ycat + (size_t)(b * Pq) * (2 * Dq);

    float x[Pq];
#pragma unroll
    for (int t = 0; t < Pq; t++) x[t] = xm[t * Dq] + pre;

    const float rf = expf(-expf(fnu[d]));
    float sf, cf;
    sincosf(ftheta[d], &sf, &cf);
    const float lfr = rf * cf, lfi = rf * sf;
    const float gfr = fgr[d], gfi = fgi[d];
    float hr = 0.f, hi = 0.f;
#pragma unroll
    for (int t = 0; t < Pq; t++) {
        float nr = fmaf(lfr, hr, fmaf(-lfi, hi, x[t]));
        float ni = fmaf(lfr, hi, lfi * hr);
        hr = nr; hi = ni;
        yc[t * (2 * Dq) + d] = gfr * hr - gfi * hi;
    }
}

// ---------------------------------------------------------------------------
// Kernel 2b: tail-sum + backward scan, all operands register-preloaded
// (R11-proven). b_off selects the batch half.
// ---------------------------------------------------------------------------
__global__ void k_scan_bwd(const float* __restrict__ mem,
                           const float* __restrict__ bnu,
                           const float* __restrict__ btheta,
                           const float* __restrict__ bgr,
                           const float* __restrict__ bgi,
                           const float* __restrict__ prefix, int b_off) {
    const int d = threadIdx.x;
    const int b = blockIdx.x + b_off;
    const float pre = prefix[d];
    const float* xm = mem + (size_t)b * Pq * Dq + d;
    float* yc = g_ycat + (size_t)(b * Pq) * (2 * Dq);

    // batch-preload chunk partials (independent LDGs)
    float pr[NCHUNK], pi[NCHUNK];
    const float* pr_p = g_pr + b * NCHUNK * Dq + d;
    const float* pi_p = g_pi + b * NCHUNK * Dq + d;
#pragma unroll
    for (int c = 0; c < NCHUNK; c++) {
        pr[c] = pr_p[c * Dq];
        pi[c] = pi_p[c * Dq];
    }
    // batch-preload x
    float x[Pq];
#pragma unroll
    for (int t = 0; t < Pq; t++) x[t] = xm[t * Dq] + pre;

    const float rb = expf(-expf(bnu[d]));
    float sb, cb;
    sincosf(btheta[d], &sb, &cb);
    const float lbr = rb * cb, lbi = rb * sb;
    const float gbr = bgr[d], gbi = bgi[d];

    // q = lam_b^CLEN via 5 squarings
    float qr = lbr, qi = lbi;
#pragma unroll
    for (int s = 0; s < 5; s++) {
        float t0 = qr * qr - qi * qi;
        qi = 2.f * qr * qi;
        qr = t0;
    }

    // tail sum S = Σ_c lam_b^{CLEN*c} * partial_c  (w-recurrence, registers)
    float wr = 1.f, wi = 0.f, Sr = 0.f, Si = 0.f;
#pragma unroll
    for (int c = 0; c < NCHUNK; c++) {
        Sr = fmaf(wr, pr[c], fmaf(-wi, pi[c], Sr));
        Si = fmaf(wr, pi[c], fmaf(wi, pr[c], Si));
        float t0 = wr * qr - wi * qi;
        wi = fmaf(wr, qi, wi * qr);
        wr = t0;
    }

    // backward scan seeded with S
    float hr = Sr, hi = Si;
#pragma unroll
    for (int t = Pq - 1; t >= 0; t--) {
        float nr = fmaf(lbr, hr, fmaf(-lbi, hi, x[t]));
        float ni = fmaf(lbr, hi, lbi * hr);
        hr = nr; hi = ni;
        yc[t * (2 * Dq) + Dq + d] = gbr * hr - gbi * hi;
    }
}

// ---------------------------------------------------------------------------
// Kernel 3a: split-K partial projection (R4/R5-proven form).
// ks_off: 0 -> k in [0,256) (y_fwd), 4 -> k in [256,512) (y_bwd).
// b_off:  batch offset, nb batches covered by grid.z.
// ---------------------------------------------------------------------------
__global__ void __launch_bounds__(256) k_proj_part(int ks_off, int b_off) {
    __shared__ float ys[KSEG * RG];   // [k][p]
    const int j  = threadIdx.x;
    const int ks = blockIdx.y + ks_off;
    const int p0 = blockIdx.x * RG;
    const int k0 = ks * KSEG;
    const int b  = blockIdx.z + b_off;

    // stage Y tile: exactly 256 entries, one per thread
    {
        const int p = j >> 6;             // KSEG == 64
        const int k = j & (KSEG - 1);
        ys[k * RG + p] =
            g_ycat[(size_t)(b * Pq + p0 + p) * (2 * Dq) + k0 + k];
    }
    __syncthreads();

    float a0 = 0.f, a1 = 0.f, a2 = 0.f, a3 = 0.f;
    const float* wp = g_Wt + (size_t)k0 * Dq + j;
#pragma unroll 8
    for (int k = 0; k < KSEG; k++) {
        const float w = wp[k * Dq];
        const float4 y = *(const float4*)&ys[k * RG];
        a0 = fmaf(y.x, w, a0);
        a1 = fmaf(y.y, w, a1);
        a2 = fmaf(y.z, w, a2);
        a3 = fmaf(y.w, w, a3);
    }

    float* o = g_part + ((size_t)(b * KSPLIT + ks) * Pq + p0) * Dq + j;
    o[0 * Dq] = a0;
    o[1 * Dq] = a1;
    o[2 * Dq] = a2;
    o[3 * Dq] = a3;
}

// ---------------------------------------------------------------------------
// Kernel 3b: reduce split-k partials + bias -> out (float4), one batch half.
// ---------------------------------------------------------------------------
__global__ void k_reduce(const float* __restrict__ bias, float* __restrict__ out,
                         int b_off) {
    const int idx = blockIdx.x * 256 + threadIdx.x
                  + b_off * (Pq * Dq / 4);         // float4 index over [B*Pq, 64]
    const int j4  = idx & 63;
    const int row = idx >> 6;         // b*Pq + p
    const int b   = row >> 6;
    const int p   = row & (Pq - 1);

    float4 s = ((const float4*)bias)[j4];
#pragma unroll
    for (int ks = 0; ks < KSPLIT; ks++) {
        const float4 v = ((const float4*)g_part)[((size_t)(b * KSPLIT + ks) * Pq + p) * (Dq / 4) + j4];
        s.x += v.x; s.y += v.y; s.z += v.z; s.w += v.w;
    }
    ((float4*)out)[idx] = s;
}

// ---------------------------------------------------------------------------
extern "C" void kernel_launch(void* const* d_in, const int* in_sizes, int n_in,
                              void* d_out, int out_size) {
    const float* memory  = (const float*)d_in[0];
    const float* ts      = (const float*)d_in[1];
    const float* fnu     = (const float*)d_in[2];
    const float* ftheta  = (const float*)d_in[3];
    const float* fgr     = (const float*)d_in[4];
    const float* fgi     = (const float*)d_in[5];
    const float* bnu     = (const float*)d_in[6];
    const float* btheta  = (const float*)d_in[7];
    const float* bgr     = (const float*)d_in[8];
    const float* bgi     = (const float*)d_in[9];
    const float* projW   = (const float*)d_in[10];
    const float* projb   = (const float*)d_in[11];
    const float* prefix  = (const float*)d_in[12];
    const float* signal  = (const float*)d_in[13];
    float* out = (float*)d_out;

    const int half_reduce_blocks = (BH * Pq * Dq / 4) / 256;

    // Fork
    cudaEventRecord(g_evRoot, 0);
    cudaStreamWaitEvent(g_s1, g_evRoot, 0);

    // Main branch: chunks for batch half A, then half B.
    k_chunks<<<dim3(NCHUNK, BH), dim3(Dq, IY)>>>(ts, bnu, btheta, signal, 0);
    cudaEventRecord(g_evC1, 0);                       // chunksA done
    k_chunks<<<dim3(NCHUNK, BH), dim3(Dq, IY)>>>(ts, bnu, btheta, signal, BH);

    // Branch A (stream g_s1): fwd chain (all batches) overlaps chunksA; then
    // the b0-3 bwd chain + reduceA overlaps chunksB.
    k_transpose<<<2 * Dq, Dq, 0, g_s1>>>(projW);
    k_scan_fwd<<<Bq, Dq, 0, g_s1>>>(memory, fnu, ftheta, fgr, fgi, prefix);
    k_proj_part<<<dim3(Pq / RG, KSPLIT / 2, Bq), Dq, 0, g_s1>>>(0, 0);
    cudaEventRecord(g_evF, g_s1);                     // fwd projection done
    cudaStreamWaitEvent(g_s1, g_evC1, 0);
    k_scan_bwd<<<BH, Dq, 0, g_s1>>>(memory, bnu, btheta, bgr, bgi, prefix, 0);
    k_proj_part<<<dim3(Pq / RG, KSPLIT / 2, BH), Dq, 0, g_s1>>>(KSPLIT / 2, 0);
    k_reduce<<<half_reduce_blocks, 256, 0, g_s1>>>(projb, out, 0);
    cudaEventRecord(g_evA, g_s1);

    // Main branch: b4-7 bwd chain after chunksB, then reduceB (needs fwd proj).
    k_scan_bwd<<<BH, Dq>>>(memory, bnu, btheta, bgr, bgi, prefix, BH);
    k_proj_part<<<dim3(Pq / RG, KSPLIT / 2, BH), Dq>>>(KSPLIT / 2, BH);
    cudaStreamWaitEvent(0, g_evF, 0);
    k_reduce<<<half_reduce_blocks, 256>>>(projb, out, BH);

    // Join: graph end depends on branch A's reduceA as well.
    cudaStreamWaitEvent(0, g_evA, 0);
}

// round 13
// speedup vs baseline: 1.2567x; 1.2567x over previous
#include <cuda_runtime.h>
#include <math.h>

// Problem constants
#define Bq 8
#define Pq 64
#define Vq 8
#define Lq 1024
#define Dq 256
#define NCHUNK 32
#define CLEN 32          // NCHUNK * CLEN == Lq
#define IY 4             // i-quarters per chunk block
#define SUB 8            // CLEN / IY
#define KSPLIT 8
#define KSEG 64          // 512 / KSPLIT
#define RG 4             // rows per projection block
#define DSPL 8           // d-splits for scan kernels (32 threads each)

// Scratch (static device globals; no allocation in kernel_launch)
__device__ float g_pr[Bq * NCHUNK * Dq];          // chunk partial sums (real)
__device__ float g_pi[Bq * NCHUNK * Dq];          // chunk partial sums (imag)
__device__ float g_ycat[Bq * Pq * 2 * Dq];        // [b, p, k] k<256: y_fwd, k>=256: y_bwd
__device__ float g_Wt[2 * Dq * Dq];               // W^T, [k][j]
__device__ float g_part[Bq * KSPLIT * Pq * Dq];   // split-k partials

// Host-side stream/events for graph fork-join (created at load time,
// before the harness takes its memory baseline; reused every call).
static cudaStream_t g_s1;
static cudaEvent_t g_evRoot, g_evA;
namespace {
struct StreamInit {
    StreamInit() {
        cudaStreamCreateWithFlags(&g_s1, cudaStreamNonBlocking);
        cudaEventCreateWithFlags(&g_evRoot, cudaEventDisableTiming);
        cudaEventCreateWithFlags(&g_evA, cudaEventDisableTiming);
    }
};
static StreamInit g_streamInit;
}

// ---------------------------------------------------------------------------
// Kernel 0: transpose proj_W [D, 2D] -> Wt [2D, D]
// ---------------------------------------------------------------------------
__global__ void k_transpose(const float* __restrict__ W) {
    int k = blockIdx.x;      // 0..511
    int j = threadIdx.x;     // 0..255
    g_Wt[k * Dq + j] = W[j * (2 * Dq) + k];
}

// ---------------------------------------------------------------------------
// Kernel 1: per-(b, chunk, d): Σ_{i<CLEN} λ_b^i * x̄[c*CLEN+i]
// 1024-thread block, 4 i-quarters combined via λ^8 Horner (R9-proven).
// ---------------------------------------------------------------------------
__global__ void __launch_bounds__(Dq * IY) k_chunks(
        const float* __restrict__ ts,
        const float* __restrict__ bnu,
        const float* __restrict__ btheta,
        const float* __restrict__ sig) {
    __shared__ float s_r[IY - 1][Dq];
    __shared__ float s_i[IY - 1][Dq];
    const int d  = threadIdx.x;
    const int ty = threadIdx.y;    // i-quarter
    const int c  = blockIdx.x;     // chunk
    const int b  = blockIdx.y;     // batch

    const float r  = expf(-expf(bnu[d]));
    float s_, c_;
    sincosf(btheta[d], &s_, &c_);
    const float lr = r * c_;
    const float li = r * s_;
    const float sg = sig[d];

    const float* base =
        ts + ((size_t)b * Lq + (size_t)c * CLEN + ty * SUB) * (Vq * Dq) + d;

    float wr = 1.f, wi = 0.f, ar = 0.f, ai = 0.f;
#pragma unroll
    for (int i = 0; i < SUB; i++) {
        const float* p = base + (size_t)i * (Vq * Dq);
        float xm = __ldg(p);
#pragma unroll
        for (int v = 1; v < Vq; v++) xm += __ldg(p + v * Dq);
        xm = fmaf(xm, 0.125f, sg);
        ar = fmaf(wr, xm, ar);
        ai = fmaf(wi, xm, ai);
        float t0 = wr * lr - wi * li;
        wi = fmaf(wr, li, wi * lr);
        wr = t0;
    }

    if (ty > 0) {
        s_r[ty - 1][d] = ar;
        s_i[ty - 1][d] = ai;
    }
    __syncthreads();

    if (ty == 0) {
        // q = lam^SUB via 3 squarings (SUB == 8)
        float qr = lr, qi = li;
#pragma unroll
        for (int s = 0; s < 3; s++) {
            float t0 = qr * qr - qi * qi;
            qi = 2.f * qr * qi;
            qr = t0;
        }
        // Horner: a = a0 + q*(a1 + q*(a2 + q*a3))
        float cr = s_r[2][d], ci = s_i[2][d];          // a3
        {
            float tr = s_r[1][d] + (qr * cr - qi * ci);
            float ti = s_i[1][d] + (qr * ci + qi * cr);
            cr = tr; ci = ti;
        }
        {
            float tr = s_r[0][d] + (qr * cr - qi * ci);
            float ti = s_i[0][d] + (qr * ci + qi * cr);
            cr = tr; ci = ti;
        }
        g_pr[(b * NCHUNK + c) * Dq + d] = ar + (qr * cr - qi * ci);
        g_pi[(b * NCHUNK + c) * Dq + d] = ai + (qr * ci + qi * cr);
    }
}

// ---------------------------------------------------------------------------
// Kernel 2a: forward scan, x register-preloaded (R11 math), but launched as
// 64 blocks of 32 threads so the DRAM preload spreads across 64 SMs.
// ---------------------------------------------------------------------------
__global__ void __launch_bounds__(32) k_scan_fwd(
        const float* __restrict__ mem,
        const float* __restrict__ fnu,
        const float* __restrict__ ftheta,
        const float* __restrict__ fgr,
        const float* __restrict__ fgi,
        const float* __restrict__ prefix) {
    const int d = blockIdx.y * 32 + threadIdx.x;
    const int b = blockIdx.x;
    const float pre = prefix[d];
    const float* xm = mem + (size_t)b * Pq * Dq + d;
    float* yc = g_ycat + (size_t)(b * Pq) * (2 * Dq);

    float x[Pq];
#pragma unroll
    for (int t = 0; t < Pq; t++) x[t] = xm[t * Dq] + pre;

    const float rf = expf(-expf(fnu[d]));
    float sf, cf;
    sincosf(ftheta[d], &sf, &cf);
    const float lfr = rf * cf, lfi = rf * sf;
    const float gfr = fgr[d], gfi = fgi[d];
    float hr = 0.f, hi = 0.f;
#pragma unroll
    for (int t = 0; t < Pq; t++) {
        float nr = fmaf(lfr, hr, fmaf(-lfi, hi, x[t]));
        float ni = fmaf(lfr, hi, lfi * hr);
        hr = nr; hi = ni;
        yc[t * (2 * Dq) + d] = gfr * hr - gfi * hi;
    }
}

// ---------------------------------------------------------------------------
// Kernel 2b: tail-sum + backward scan, register-preloaded (R11 math),
// launched as 64 blocks of 32 threads for SM spread.
// ---------------------------------------------------------------------------
__global__ void __launch_bounds__(32) k_scan_bwd(
        const float* __restrict__ mem,
        const float* __restrict__ bnu,
        const float* __restrict__ btheta,
        const float* __restrict__ bgr,
        const float* __restrict__ bgi,
        const float* __restrict__ prefix) {
    const int d = blockIdx.y * 32 + threadIdx.x;
    const int b = blockIdx.x;
    const float pre = prefix[d];
    const float* xm = mem + (size_t)b * Pq * Dq + d;
    float* yc = g_ycat + (size_t)(b * Pq) * (2 * Dq);

    // batch-preload chunk partials (independent LDGs)
    float pr[NCHUNK], pi[NCHUNK];
    const float* pr_p = g_pr + b * NCHUNK * Dq + d;
    const float* pi_p = g_pi + b * NCHUNK * Dq + d;
#pragma unroll
    for (int c = 0; c < NCHUNK; c++) {
        pr[c] = pr_p[c * Dq];
        pi[c] = pi_p[c * Dq];
    }
    // batch-preload x
    float x[Pq];
#pragma unroll
    for (int t = 0; t < Pq; t++) x[t] = xm[t * Dq] + pre;

    const float rb = expf(-expf(bnu[d]));
    float sb, cb;
    sincosf(btheta[d], &sb, &cb);
    const float lbr = rb * cb, lbi = rb * sb;
    const float gbr = bgr[d], gbi = bgi[d];

    // q = lam_b^CLEN via 5 squarings
    float qr = lbr, qi = lbi;
#pragma unroll
    for (int s = 0; s < 5; s++) {
        float t0 = qr * qr - qi * qi;
        qi = 2.f * qr * qi;
        qr = t0;
    }

    // tail sum S = Σ_c lam_b^{CLEN*c} * partial_c  (w-recurrence, registers)
    float wr = 1.f, wi = 0.f, Sr = 0.f, Si = 0.f;
#pragma unroll
    for (int c = 0; c < NCHUNK; c++) {
        Sr = fmaf(wr, pr[c], fmaf(-wi, pi[c], Sr));
        Si = fmaf(wr, pi[c], fmaf(wi, pr[c], Si));
        float t0 = wr * qr - wi * qi;
        wi = fmaf(wr, qi, wi * qr);
        wr = t0;
    }

    // backward scan seeded with S
    float hr = Sr, hi = Si;
#pragma unroll
    for (int t = Pq - 1; t >= 0; t--) {
        float nr = fmaf(lbr, hr, fmaf(-lbi, hi, x[t]));
        float ni = fmaf(lbr, hi, lbi * hr);
        hr = nr; hi = ni;
        yc[t * (2 * Dq) + Dq + d] = gbr * hr - gbi * hi;
    }
}

// ---------------------------------------------------------------------------
// Kernel 3a: split-K partial projection (R4/R5-proven form).
// ks_off=0 -> k in [0,256) (y_fwd only); ks_off=4 -> k in [256,512) (y_bwd).
// ---------------------------------------------------------------------------
__global__ void __launch_bounds__(256) k_proj_part(int ks_off) {
    __shared__ float ys[KSEG * RG];   // [k][p]
    const int j  = threadIdx.x;
    const int ks = blockIdx.y + ks_off;
    const int p0 = blockIdx.x * RG;
    const int k0 = ks * KSEG;
    const int b  = blockIdx.z;

    // stage Y tile: exactly 256 entries, one per thread
    {
        const int p = j >> 6;             // KSEG == 64
        const int k = j & (KSEG - 1);
        ys[k * RG + p] =
            g_ycat[(size_t)(b * Pq + p0 + p) * (2 * Dq) + k0 + k];
    }
    __syncthreads();

    float a0 = 0.f, a1 = 0.f, a2 = 0.f, a3 = 0.f;
    const float* wp = g_Wt + (size_t)k0 * Dq + j;
#pragma unroll 8
    for (int k = 0; k < KSEG; k++) {
        const float w = wp[k * Dq];
        const float4 y = *(const float4*)&ys[k * RG];
        a0 = fmaf(y.x, w, a0);
        a1 = fmaf(y.y, w, a1);
        a2 = fmaf(y.z, w, a2);
        a3 = fmaf(y.w, w, a3);
    }

    float* o = g_part + ((size_t)(b * KSPLIT + ks) * Pq + p0) * Dq + j;
    o[0 * Dq] = a0;
    o[1 * Dq] = a1;
    o[2 * Dq] = a2;
    o[3 * Dq] = a3;
}

// ---------------------------------------------------------------------------
// Kernel 3b: reduce split-k partials + bias -> out (float4)
// ---------------------------------------------------------------------------
__global__ void k_reduce(const float* __restrict__ bias, float* __restrict__ out) {
    const int idx = blockIdx.x * 256 + threadIdx.x;  // float4 index over [B*Pq, 64]
    const int j4  = idx & 63;
    const int row = idx >> 6;         // b*Pq + p
    const int b   = row >> 6;
    const int p   = row & (Pq - 1);

    float4 s = ((const float4*)bias)[j4];
#pragma unroll
    for (int ks = 0; ks < KSPLIT; ks++) {
        const float4 v = ((const float4*)g_part)[((size_t)(b * KSPLIT + ks) * Pq + p) * (Dq / 4) + j4];
        s.x += v.x; s.y += v.y; s.z += v.z; s.w += v.w;
    }
    ((float4*)out)[idx] = s;
}

// ---------------------------------------------------------------------------
extern "C" void kernel_launch(void* const* d_in, const int* in_sizes, int n_in,
                              void* d_out, int out_size) {
    const float* memory  = (const float*)d_in[0];
    const float* ts      = (const float*)d_in[1];
    const float* fnu     = (const float*)d_in[2];
    const float* ftheta  = (const float*)d_in[3];
    const float* fgr     = (const float*)d_in[4];
    const float* fgi     = (const float*)d_in[5];
    const float* bnu     = (const float*)d_in[6];
    const float* btheta  = (const float*)d_in[7];
    const float* bgr     = (const float*)d_in[8];
    const float* bgi     = (const float*)d_in[9];
    const float* projW   = (const float*)d_in[10];
    const float* projb   = (const float*)d_in[11];
    const float* prefix  = (const float*)d_in[12];
    const float* signal  = (const float*)d_in[13];
    float* out = (float*)d_out;

    // Fork: branch A (transpose -> fwd scan -> fwd-half projection) is
    // independent of the DRAM-bound k_chunks and overlaps it.
    cudaEventRecord(g_evRoot, 0);
    cudaStreamWaitEvent(g_s1, g_evRoot, 0);

    // Branch A (stream g_s1)
    k_transpose<<<2 * Dq, Dq, 0, g_s1>>>(projW);
    k_scan_fwd<<<dim3(Bq, DSPL), 32, 0, g_s1>>>(memory, fnu, ftheta, fgr, fgi, prefix);
    k_proj_part<<<dim3(Pq / RG, KSPLIT / 2, Bq), Dq, 0, g_s1>>>(0);
    cudaEventRecord(g_evA, g_s1);

    // Main branch (capture stream)
    k_chunks<<<dim3(NCHUNK, Bq), dim3(Dq, IY)>>>(ts, bnu, btheta, signal);
    k_scan_bwd<<<dim3(Bq, DSPL), 32>>>(memory, bnu, btheta, bgr, bgi, prefix);
    k_proj_part<<<dim3(Pq / RG, KSPLIT / 2, Bq), Dq>>>(KSPLIT / 2);

    // Join, then final reduce
    cudaStreamWaitEvent(0, g_evA, 0);
    k_reduce<<<(Bq * Pq * Dq / 4) / 256, 256>>>(projb, out);
}